// round 12
// baseline (speedup 1.0000x reference)
#include <cuda_runtime.h>
#include <cuda_fp16.h>
#include <math.h>

#define NB 4
#define NL 2048
#define ND 1024
#define NH 16
#define DH 64
#define ND3 (3*ND)

// Scratch (allocation-free: __device__ globals)
__device__ __half g_xh    [(size_t)NB*NL*ND];    // x fp16
__device__ __half g_wqkvh [(size_t)ND3*ND];      // W_qkv^T fp16 [N][K]
__device__ __half g_wprojh[(size_t)ND*ND];       // W_proj^T fp16 [N][K]
__device__ __half g_qh    [(size_t)NB*NH*NL*DH]; // roped Q fp16 [b,h,l,d]
__device__ __half g_kh    [(size_t)NB*NH*NL*DH]; // roped K fp16 [b,h,l,d]
__device__ __half g_vh    [(size_t)NB*NH*NL*DH]; // V fp16 [b,h,l,d]
__device__ __half g_attnh [(size_t)NB*NL*ND];    // attn out fp16 [b,l,nd]

__device__ __forceinline__ unsigned pack2(float a, float b) {
    __half2 h = __floats2half2_rn(a, b);
    return *reinterpret_cast<unsigned*>(&h);
}
__device__ __forceinline__ float ex2(float x) {
    float y;
    asm("ex2.approx.f32 %0, %1;" : "=f"(y) : "f"(x));
    return y;
}
__device__ __forceinline__ void mma16(float* d, const unsigned* a,
                                      unsigned b0, unsigned b1) {
    asm volatile(
        "mma.sync.aligned.m16n8k16.row.col.f32.f16.f16.f32 "
        "{%0,%1,%2,%3}, {%4,%5,%6,%7}, {%8,%9}, {%0,%1,%2,%3};"
        : "+f"(d[0]), "+f"(d[1]), "+f"(d[2]), "+f"(d[3])
        : "r"(a[0]), "r"(a[1]), "r"(a[2]), "r"(a[3]), "r"(b0), "r"(b1));
}
__device__ __forceinline__ void ldsm4(unsigned* r, unsigned addr) {
    asm volatile(
        "ldmatrix.sync.aligned.m8n8.x4.shared.b16 {%0,%1,%2,%3}, [%4];"
        : "=r"(r[0]), "=r"(r[1]), "=r"(r[2]), "=r"(r[3]) : "r"(addr));
}
__device__ __forceinline__ void ldsm4t(unsigned* r, unsigned addr) {
    asm volatile(
        "ldmatrix.sync.aligned.m8n8.x4.trans.shared.b16 {%0,%1,%2,%3}, [%4];"
        : "=r"(r[0]), "=r"(r[1]), "=r"(r[2]), "=r"(r[3]) : "r"(addr));
}
__device__ __forceinline__ void cpa16(unsigned dst, const void* src) {
    asm volatile("cp.async.cg.shared.global [%0], [%1], 16;"
                 :: "r"(dst), "l"(src));
}
#define CP_COMMIT() asm volatile("cp.async.commit_group;")
#define CP_WAIT1()  asm volatile("cp.async.wait_group 1;")
#define CP_WAIT0()  asm volatile("cp.async.wait_group 0;")

// ---------------------------------------------------------------------------
// Prep: fp32 -> fp16 bulk convert
// ---------------------------------------------------------------------------
__global__ void conv_h(const float* __restrict__ src,
                       __half* __restrict__ dst, int n8)
{
    int i = blockIdx.x * blockDim.x + threadIdx.x;
    if (i < n8) {
        float4 a = ((const float4*)src)[2 * i];
        float4 b = ((const float4*)src)[2 * i + 1];
        uint4 w;
        w.x = pack2(a.x, a.y); w.y = pack2(a.z, a.w);
        w.z = pack2(b.x, b.y); w.w = pack2(b.z, b.w);
        ((uint4*)dst)[i] = w;
    }
}

// ---------------------------------------------------------------------------
// Prep: W [K][N] fp32 -> Wt [N][K] fp16
// ---------------------------------------------------------------------------
__global__ __launch_bounds__(256) void wtrans_h(
    const float* __restrict__ W, __half* __restrict__ Wt, int K, int N)
{
    __shared__ float sm[32][33];
    int tx = threadIdx.x & 31, ty = threadIdx.x >> 5;
    int n0 = blockIdx.x * 32, k0 = blockIdx.y * 32;
#pragma unroll
    for (int j = 0; j < 4; j++)
        sm[ty + 8 * j][tx] = W[(size_t)(k0 + ty + 8 * j) * N + n0 + tx];
    __syncthreads();
#pragma unroll
    for (int j = 0; j < 4; j++)
        Wt[(size_t)(n0 + ty + 8 * j) * K + k0 + tx] =
            __float2half(sm[tx][ty + 8 * j]);
}

// ---------------------------------------------------------------------------
// FP16 GEMM: C[M][N] = A[M][K] @ Bt[N][K]^T + bias[N].
// CTA tile 128(M) x 256(N), BK=32. 8 warps in 2(m) x 4(n) grid, warp tile
// 64x64 (4 mf x 8 nf). LDG reg-prefetch + double-buffered dynamic SMEM.
// 16 LDSM.x4 per 64 MMAs per warp/k-tile (128 B/MMA).
// mode 0: C fp32 [M][N].  mode 1: fused QKV bias+split+RoPE epilogue.
// ---------------------------------------------------------------------------
#define A_H 5120            /* A stage halfs: 128*40 */
#define B_H 10240           /* B stage halfs: 256*40 */
#define STG_H (A_H + B_H)   /* 15360 halfs per stage */
#define GEMM_SMEM (2 * STG_H * 2)   /* 61440 bytes */

__global__ __launch_bounds__(256, 1) void gemm_h(
    const __half* __restrict__ A, const __half* __restrict__ Bt,
    const float* __restrict__ bias, float* __restrict__ Cf,
    __half* __restrict__ qh, __half* __restrict__ kh,
    __half* __restrict__ vh,
    int M, int N, int K, int mode)
{
    extern __shared__ __half sh[];
    const int tid = threadIdx.x;
    const int lane = tid & 31, wid = tid >> 5;
    const int wm = wid >> 2, wn = wid & 3;
    const int g = lane >> 2, t = lane & 3;

    const __half* Ag = A + (size_t)blockIdx.y * 128 * K;
    const __half* Bg = Bt + (size_t)blockIdx.x * 256 * K;

    float acc[4][8][4];
#pragma unroll
    for (int mf = 0; mf < 4; mf++)
#pragma unroll
        for (int nf = 0; nf < 8; nf++)
#pragma unroll
            for (int i = 0; i < 4; i++) acc[mf][nf][i] = 0.f;

    const int crow = tid >> 2, coff = (tid & 3) * 8;

    uint4 ar[2], br[4];
    ar[0] = *(const uint4*)(Ag + (size_t)crow * K + coff);
    ar[1] = *(const uint4*)(Ag + (size_t)(crow + 64) * K + coff);
#pragma unroll
    for (int p = 0; p < 4; p++)
        br[p] = *(const uint4*)(Bg + (size_t)(crow + p * 64) * K + coff);

    const int arow_l = ((lane >> 3) & 1) * 8 + (lane & 7);
    const int akoff_l = (lane >> 4) * 8;
    const int brow_l = ((lane >> 4) & 1) * 8 + (lane & 7);
    const int bkoff_l = ((lane >> 3) & 1) * 8;

    const unsigned sh0 = (unsigned)__cvta_generic_to_shared(sh);
    const int nt = K / 32;
    for (int tile = 0; tile < nt; tile++) {
        const int buf = tile & 1;
        {
            __half* as = sh + buf * STG_H;
            __half* bs = as + A_H;
            *(uint4*)(as + crow * 40 + coff) = ar[0];
            *(uint4*)(as + (crow + 64) * 40 + coff) = ar[1];
#pragma unroll
            for (int p = 0; p < 4; p++)
                *(uint4*)(bs + (crow + p * 64) * 40 + coff) = br[p];
        }
        if (tile + 1 < nt) {
            const __half* An = Ag + (tile + 1) * 32;
            const __half* Bn = Bg + (tile + 1) * 32;
            ar[0] = *(const uint4*)(An + (size_t)crow * K + coff);
            ar[1] = *(const uint4*)(An + (size_t)(crow + 64) * K + coff);
#pragma unroll
            for (int p = 0; p < 4; p++)
                br[p] = *(const uint4*)(Bn + (size_t)(crow + p * 64) * K + coff);
        }
        __syncthreads();

        const unsigned as0 = sh0 + buf * (STG_H * 2);
        const unsigned bs0 = as0 + A_H * 2;
#pragma unroll
        for (int kc = 0; kc < 2; kc++) {
            unsigned a[4][4];
#pragma unroll
            for (int mf = 0; mf < 4; mf++)
                ldsm4(a[mf], as0 + ((wm * 64 + mf * 16 + arow_l) * 40
                                    + kc * 16 + akoff_l) * 2);
#pragma unroll
            for (int nfp = 0; nfp < 4; nfp++) {
                unsigned bk[4];
                ldsm4(bk, bs0 + ((wn * 64 + nfp * 16 + brow_l) * 40
                                 + kc * 16 + bkoff_l) * 2);
#pragma unroll
                for (int mf = 0; mf < 4; mf++) {
                    mma16(acc[mf][2 * nfp],     a[mf], bk[0], bk[1]);
                    mma16(acc[mf][2 * nfp + 1], a[mf], bk[2], bk[3]);
                }
            }
        }
        __syncthreads();
    }

    if (mode == 0) {
#pragma unroll
        for (int mf = 0; mf < 4; mf++) {
            int row = blockIdx.y * 128 + wm * 64 + mf * 16 + g;
#pragma unroll
            for (int nf = 0; nf < 8; nf++) {
                int col = blockIdx.x * 256 + wn * 64 + nf * 8 + 2 * t;
                float b0 = bias[col], b1 = bias[col + 1];
                *(float2*)(Cf + (size_t)row * N + col) =
                    make_float2(acc[mf][nf][0] + b0, acc[mf][nf][1] + b1);
                *(float2*)(Cf + (size_t)(row + 8) * N + col) =
                    make_float2(acc[mf][nf][2] + b0, acc[mf][nf][3] + b1);
            }
        }
    } else {
        // fused QKV epilogue: bias + split + rope -> [b,h,l,d] fp16
#pragma unroll
        for (int nf = 0; nf < 8; nf++) {
            const int cg = blockIdx.x * 256 + wn * 64 + nf * 8 + 2 * t;
            const int sec = cg >> 10;          // 0=q, 1=k, 2=v
            const int d10 = cg & 1023;
            const int h = d10 >> 6, d = d10 & 63;
            const float b0 = bias[cg], b1 = bias[cg + 1];
            float inv = 0.f;
            if (sec < 2)
                inv = powf(10000.0f, -(float)d / (float)DH);  // d even = 2*i
#pragma unroll
            for (int mf = 0; mf < 4; mf++) {
#pragma unroll
                for (int rr = 0; rr < 2; rr++) {
                    int row = blockIdx.y * 128 + wm * 64 + mf * 16 + g + rr * 8;
                    int b = row >> 11, l = row & (NL - 1);
                    float v0 = acc[mf][nf][2 * rr] + b0;
                    float v1 = acc[mf][nf][2 * rr + 1] + b1;
                    size_t o = ((size_t)(b * NH + h) * NL + l) * DH + d;
                    if (sec == 2) {
                        *(unsigned*)(vh + o) = pack2(v0, v1);
                    } else {
                        float sn, cs;
                        sincosf((float)l * inv, &sn, &cs);
                        unsigned w = pack2(v0 * cs - v1 * sn,
                                           v0 * sn + v1 * cs);
                        *(unsigned*)((sec == 0 ? qh : kh) + o) = w;
                    }
                }
            }
        }
    }
}

// ---------------------------------------------------------------------------
// FP16 flash attention (unchanged from R11), fixed-max softmax.
// ---------------------------------------------------------------------------
#define QT 256
#define KT 64
#define STR 72   /* halfs per row */
#define SCL 0.1803368801111244f   /* 0.125 * log2(e) */

__global__ __launch_bounds__(256, 1) void attn_h(
    const __half* __restrict__ Qg, const __half* __restrict__ Kg,
    const __half* __restrict__ Vg, const int* __restrict__ amask,
    __half* __restrict__ outh)
{
    extern __shared__ __half sa[];
    const unsigned qs0 = (unsigned)__cvta_generic_to_shared(sa);
    const unsigned ks0 = qs0 + QT * STR * 2;
    const unsigned vs0 = ks0 + 2 * KT * STR * 2;
    float* msk = (float*)(sa + QT * STR + 4 * KT * STR);

    const int tid = threadIdx.x;
    const int lane = tid & 31, wid = tid >> 5;
    const int g = lane >> 2, t = lane & 3;
    const int qt = (gridDim.x - 1) - blockIdx.x;   // heavy tiles first
    const int bh = blockIdx.y;
    const int b = bh >> 4, h = bh & 15;
    const int q0 = qt * QT;
    const int ktmax = 4 * qt + 3;

    const __half* Qp = Qg + ((size_t)bh * NL + q0) * DH;
    const __half* Kp = Kg + (size_t)bh * NL * DH;
    const __half* Vp = Vg + (size_t)bh * NL * DH;

    auto copy_kv = [&](int kt_, int bf) {
        unsigned kd = ks0 + bf * (KT * STR * 2);
        unsigned vd = vs0 + bf * (KT * STR * 2);
        const __half* Ksrc = Kp + (size_t)kt_ * KT * DH;
        const __half* Vsrc = Vp + (size_t)kt_ * KT * DH;
#pragma unroll
        for (int i = 0; i < 2; i++) {
            int c = tid + i * 256;
            int r = c >> 3, o8 = (c & 7) * 8;
            cpa16(kd + (r * STR + o8) * 2, Ksrc + r * DH + o8);
            cpa16(vd + (r * STR + o8) * 2, Vsrc + r * DH + o8);
        }
        if (tid < KT)
            msk[bf * KT + tid] =
                amask[b * NL + kt_ * KT + tid] ? 0.f : -1e30f;
    };

    // prologue: Q + tile 0
#pragma unroll
    for (int i = 0; i < 8; i++) {
        int c = tid + i * 256;
        int r = c >> 3, o8 = (c & 7) * 8;
        cpa16(qs0 + (r * STR + o8) * 2, Qp + (size_t)r * DH + o8);
    }
    copy_kv(0, 0);
    CP_COMMIT();

    const int arow_l = ((lane >> 3) & 1) * 8 + (lane & 7);
    const int akoff_l = (lane >> 4) * 8;
    const int krow_l = ((lane >> 4) & 1) * 8 + (lane & 7);
    const int kkoff_l = ((lane >> 3) & 1) * 8;
    const int vkey_l = ((lane >> 4) & 1) * 8 + (lane & 7);
    const int vdoff_l = ((lane >> 3) & 1) * 8;

    unsigned qb[2];
#pragma unroll
    for (int mf = 0; mf < 2; mf++)
        qb[mf] = qs0 + ((wid * 32 + mf * 16 + arow_l) * STR + akoff_l) * 2;
    unsigned kbb[4], vbb[4];
#pragma unroll
    for (int j = 0; j < 4; j++) {
        kbb[j] = ks0 + ((j * 16 + krow_l) * STR + kkoff_l) * 2;
        vbb[j] = vs0 + (vkey_l * STR + j * 16 + vdoff_l) * 2;
    }
    const unsigned bufB = KT * STR * 2;

    float o[2][8][4];
#pragma unroll
    for (int mf = 0; mf < 2; mf++)
#pragma unroll
        for (int nf = 0; nf < 8; nf++)
#pragma unroll
            for (int i = 0; i < 4; i++) o[mf][nf][i] = 0.f;
    float l_acc[2][2] = {{0.f, 0.f}, {0.f, 0.f}};

    unsigned qreg[4][2][4];
    int buf = 0;
    for (int kt = 0; kt <= ktmax; kt++) {
        if (kt < ktmax) {
            copy_kv(kt + 1, buf ^ 1);
            CP_COMMIT();
            CP_WAIT1();
        } else {
            CP_WAIT0();
        }
        __syncthreads();

        if (kt == 0) {
#pragma unroll
            for (int kc = 0; kc < 4; kc++) {
                ldsm4(qreg[kc][0], qb[0] + kc * 32);
                ldsm4(qreg[kc][1], qb[1] + kc * 32);
            }
        }

        const unsigned kofs = buf * bufB;
        const float* mb = msk + buf * KT;

        float s[2][8][4];
#pragma unroll
        for (int mf = 0; mf < 2; mf++)
#pragma unroll
            for (int nf = 0; nf < 8; nf++)
#pragma unroll
                for (int i = 0; i < 4; i++) s[mf][nf][i] = 0.f;

#pragma unroll
        for (int kc = 0; kc < 4; kc++) {
            unsigned bk[4];
#pragma unroll
            for (int nfp = 0; nfp < 4; nfp++) {
                ldsm4(bk, kbb[nfp] + kofs + kc * 32);
                mma16(s[0][2 * nfp],     qreg[kc][0], bk[0], bk[1]);
                mma16(s[1][2 * nfp],     qreg[kc][1], bk[0], bk[1]);
                mma16(s[0][2 * nfp + 1], qreg[kc][0], bk[2], bk[3]);
                mma16(s[1][2 * nfp + 1], qreg[kc][1], bk[2], bk[3]);
            }
        }

        const bool diag = (kt * KT + KT - 1 > q0);

#pragma unroll
        for (int mf = 0; mf < 2; mf++) {
            const int rlo = q0 + wid * 32 + mf * 16 + g;
            const int rhi = rlo + 8;
            float sum0 = 0.f, sum1 = 0.f;
#pragma unroll
            for (int nf = 0; nf < 8; nf++) {
                int c = kt * KT + nf * 8 + 2 * t;
                float mk0 = mb[nf * 8 + 2 * t];
                float mk1 = mb[nf * 8 + 2 * t + 1];
                float* sv = s[mf][nf];
                sv[0] = sv[0] * SCL + mk0;
                sv[1] = sv[1] * SCL + mk1;
                sv[2] = sv[2] * SCL + mk0;
                sv[3] = sv[3] * SCL + mk1;
                if (diag) {
                    if (c     > rlo) sv[0] = -1e30f;
                    if (c + 1 > rlo) sv[1] = -1e30f;
                    if (c     > rhi) sv[2] = -1e30f;
                    if (c + 1 > rhi) sv[3] = -1e30f;
                }
                sv[0] = ex2(sv[0]); sum0 += sv[0];
                sv[1] = ex2(sv[1]); sum0 += sv[1];
                sv[2] = ex2(sv[2]); sum1 += sv[2];
                sv[3] = ex2(sv[3]); sum1 += sv[3];
            }
            l_acc[mf][0] += sum0;
            l_acc[mf][1] += sum1;
        }

#pragma unroll
        for (int kc = 0; kc < 4; kc++) {
            unsigned pa[2][4];
#pragma unroll
            for (int mf = 0; mf < 2; mf++) {
                pa[mf][0] = pack2(s[mf][2 * kc][0],     s[mf][2 * kc][1]);
                pa[mf][1] = pack2(s[mf][2 * kc][2],     s[mf][2 * kc][3]);
                pa[mf][2] = pack2(s[mf][2 * kc + 1][0], s[mf][2 * kc + 1][1]);
                pa[mf][3] = pack2(s[mf][2 * kc + 1][2], s[mf][2 * kc + 1][3]);
            }
#pragma unroll
            for (int db = 0; db < 4; db++) {
                unsigned bv[4];
                ldsm4t(bv, vbb[db] + kofs + kc * (16 * STR * 2));
                mma16(o[0][2 * db],     pa[0], bv[0], bv[2]);
                mma16(o[1][2 * db],     pa[1], bv[0], bv[2]);
                mma16(o[0][2 * db + 1], pa[0], bv[1], bv[3]);
                mma16(o[1][2 * db + 1], pa[1], bv[1], bv[3]);
            }
        }
        __syncthreads();
        buf ^= 1;
    }

#pragma unroll
    for (int mf = 0; mf < 2; mf++) {
        float s0 = l_acc[mf][0], s1 = l_acc[mf][1];
        s0 += __shfl_xor_sync(0xffffffffu, s0, 1);
        s0 += __shfl_xor_sync(0xffffffffu, s0, 2);
        s1 += __shfl_xor_sync(0xffffffffu, s1, 1);
        s1 += __shfl_xor_sync(0xffffffffu, s1, 2);
        float inv0 = 1.f / s0, inv1 = 1.f / s1;
        int rlo = q0 + wid * 32 + mf * 16 + g;
        __half* op = outh + ((size_t)b * NL + rlo) * ND + h * DH;
#pragma unroll
        for (int nf = 0; nf < 8; nf++) {
            int col = nf * 8 + 2 * t;
            *(unsigned*)(op + col) =
                pack2(o[mf][nf][0] * inv0, o[mf][nf][1] * inv0);
            *(unsigned*)(op + (size_t)8 * ND + col) =
                pack2(o[mf][nf][2] * inv1, o[mf][nf][3] * inv1);
        }
    }
}

// ---------------------------------------------------------------------------
extern "C" void kernel_launch(void* const* d_in, const int* in_sizes, int n_in,
                              void* d_out, int out_size)
{
    const float* x     = (const float*)d_in[0];
    const float* Wqkv  = (const float*)d_in[1];
    const float* bqkv  = (const float*)d_in[2];
    const float* Wproj = (const float*)d_in[3];
    const float* bproj = (const float*)d_in[4];
    const int*   amask = (const int*)d_in[5];
    float* out = (float*)d_out;

    __half *xh, *wqkvh, *wprojh, *qh, *kh, *vh, *attnh;
    cudaGetSymbolAddress((void**)&xh,     g_xh);
    cudaGetSymbolAddress((void**)&wqkvh,  g_wqkvh);
    cudaGetSymbolAddress((void**)&wprojh, g_wprojh);
    cudaGetSymbolAddress((void**)&qh,     g_qh);
    cudaGetSymbolAddress((void**)&kh,     g_kh);
    cudaGetSymbolAddress((void**)&vh,     g_vh);
    cudaGetSymbolAddress((void**)&attnh,  g_attnh);

    cudaFuncSetAttribute(gemm_h,
                         cudaFuncAttributeMaxDynamicSharedMemorySize,
                         GEMM_SMEM);
    const int attn_smem = (QT * STR + 4 * KT * STR) * 2 + 2 * KT * 4;
    cudaFuncSetAttribute(attn_h,
                         cudaFuncAttributeMaxDynamicSharedMemorySize,
                         attn_smem);

    // Prep: convert x, transpose+convert weights
    int n8 = (NB * NL * ND) / 8;
    conv_h<<<(n8 + 255) / 256, 256>>>(x, xh, n8);
    wtrans_h<<<dim3(ND3 / 32, ND / 32), 256>>>(Wqkv, wqkvh, ND, ND3);
    wtrans_h<<<dim3(ND / 32, ND / 32), 256>>>(Wproj, wprojh, ND, ND);

    // 1) QKV projection with fused bias+split+RoPE -> qh/kh/vh [b,h,l,d]
    gemm_h<<<dim3(ND3 / 256, (NB * NL) / 128), 256, GEMM_SMEM>>>(
        xh, wqkvh, bqkv, nullptr, qh, kh, vh, NB * NL, ND3, ND, 1);

    // 2) Attention -> fp16 [b,l,nd]
    attn_h<<<dim3(NL / QT, NB * NH), 256, attn_smem>>>(
        qh, kh, vh, amask, attnh);

    // 3) Output projection -> fp32
    gemm_h<<<dim3(ND / 256, (NB * NL) / 128), 256, GEMM_SMEM>>>(
        attnh, wprojh, bproj, out, nullptr, nullptr, nullptr,
        NB * NL, ND, ND, 0);
}

// round 13
// speedup vs baseline: 1.1275x; 1.1275x over previous
#include <cuda_runtime.h>
#include <cuda_fp16.h>
#include <math.h>

#define NB 4
#define NL 2048
#define ND 1024
#define NH 16
#define DH 64
#define ND3 (3*ND)

// Scratch (allocation-free: __device__ globals)
__device__ __half g_xh    [(size_t)NB*NL*ND];    // x fp16
__device__ __half g_wqkvh [(size_t)ND3*ND];      // W_qkv^T fp16 [N][K]
__device__ __half g_wprojh[(size_t)ND*ND];       // W_proj^T fp16 [N][K]
__device__ __half g_qh    [(size_t)NB*NH*NL*DH]; // roped Q fp16 [b,h,l,d]
__device__ __half g_kh    [(size_t)NB*NH*NL*DH]; // roped K fp16 [b,h,l,d]
__device__ __half g_vh    [(size_t)NB*NH*NL*DH]; // V fp16 [b,h,l,d]
__device__ __half g_attnh [(size_t)NB*NL*ND];    // attn out fp16 [b,l,nd]

__device__ __forceinline__ unsigned pack2(float a, float b) {
    __half2 h = __floats2half2_rn(a, b);
    return *reinterpret_cast<unsigned*>(&h);
}
__device__ __forceinline__ float ex2(float x) {
    float y;
    asm("ex2.approx.f32 %0, %1;" : "=f"(y) : "f"(x));
    return y;
}
__device__ __forceinline__ void mma16(float* d, const unsigned* a,
                                      unsigned b0, unsigned b1) {
    asm volatile(
        "mma.sync.aligned.m16n8k16.row.col.f32.f16.f16.f32 "
        "{%0,%1,%2,%3}, {%4,%5,%6,%7}, {%8,%9}, {%0,%1,%2,%3};"
        : "+f"(d[0]), "+f"(d[1]), "+f"(d[2]), "+f"(d[3])
        : "r"(a[0]), "r"(a[1]), "r"(a[2]), "r"(a[3]), "r"(b0), "r"(b1));
}
__device__ __forceinline__ void ldsm4(unsigned* r, unsigned addr) {
    asm volatile(
        "ldmatrix.sync.aligned.m8n8.x4.shared.b16 {%0,%1,%2,%3}, [%4];"
        : "=r"(r[0]), "=r"(r[1]), "=r"(r[2]), "=r"(r[3]) : "r"(addr));
}
__device__ __forceinline__ void ldsm4t(unsigned* r, unsigned addr) {
    asm volatile(
        "ldmatrix.sync.aligned.m8n8.x4.trans.shared.b16 {%0,%1,%2,%3}, [%4];"
        : "=r"(r[0]), "=r"(r[1]), "=r"(r[2]), "=r"(r[3]) : "r"(addr));
}
__device__ __forceinline__ void cpa16(unsigned dst, const void* src) {
    asm volatile("cp.async.cg.shared.global [%0], [%1], 16;"
                 :: "r"(dst), "l"(src));
}
#define CP_COMMIT() asm volatile("cp.async.commit_group;")
#define CP_WAIT1()  asm volatile("cp.async.wait_group 1;")
#define CP_WAIT0()  asm volatile("cp.async.wait_group 0;")

// ---------------------------------------------------------------------------
// Prep: fp32 -> fp16 bulk convert
// ---------------------------------------------------------------------------
__global__ void conv_h(const float* __restrict__ src,
                       __half* __restrict__ dst, int n8)
{
    int i = blockIdx.x * blockDim.x + threadIdx.x;
    if (i < n8) {
        float4 a = ((const float4*)src)[2 * i];
        float4 b = ((const float4*)src)[2 * i + 1];
        uint4 w;
        w.x = pack2(a.x, a.y); w.y = pack2(a.z, a.w);
        w.z = pack2(b.x, b.y); w.w = pack2(b.z, b.w);
        ((uint4*)dst)[i] = w;
    }
}

// ---------------------------------------------------------------------------
// Prep: W [K][N] fp32 -> Wt [N][K] fp16
// ---------------------------------------------------------------------------
__global__ __launch_bounds__(256) void wtrans_h(
    const float* __restrict__ W, __half* __restrict__ Wt, int K, int N)
{
    __shared__ float sm[32][33];
    int tx = threadIdx.x & 31, ty = threadIdx.x >> 5;
    int n0 = blockIdx.x * 32, k0 = blockIdx.y * 32;
#pragma unroll
    for (int j = 0; j < 4; j++)
        sm[ty + 8 * j][tx] = W[(size_t)(k0 + ty + 8 * j) * N + n0 + tx];
    __syncthreads();
#pragma unroll
    for (int j = 0; j < 4; j++)
        Wt[(size_t)(n0 + ty + 8 * j) * K + k0 + tx] =
            __float2half(sm[tx][ty + 8 * j]);
}

// ---------------------------------------------------------------------------
// FP16 GEMM: C[M][N] = A[M][K] @ Bt[N][K]^T + bias[N].
// CTA tile 128x128, BK=32. 4 warps (128 thr) in 2x2 grid, warp tile 64x64.
// LDG reg-prefetch + double-buffered static SMEM, 1 sync/tile. 2 CTAs/SM:
// two independent barrier domains overlap each other's stalls while keeping
// the 64x64 tile's 0.25 ldsm/mma ratio.
// mode 0: C fp32 [M][N].  mode 1: fused QKV bias+split+RoPE epilogue.
// ---------------------------------------------------------------------------
__global__ __launch_bounds__(128, 2) void gemm_h(
    const __half* __restrict__ A, const __half* __restrict__ Bt,
    const float* __restrict__ bias, float* __restrict__ Cf,
    __half* __restrict__ qh, __half* __restrict__ kh,
    __half* __restrict__ vh,
    int M, int N, int K, int mode)
{
    __shared__ __half sh[2][2][128 * 40];   // [buf][A/B][row*40+k]  40KB
    const int tid = threadIdx.x;
    const int lane = tid & 31, wid = tid >> 5;
    const int wm = wid >> 1, wn = wid & 1;
    const int g = lane >> 2, t = lane & 3;

    const __half* Ag = A + (size_t)blockIdx.y * 128 * K;
    const __half* Bg = Bt + (size_t)blockIdx.x * 128 * K;

    float acc[4][8][4];
#pragma unroll
    for (int mf = 0; mf < 4; mf++)
#pragma unroll
        for (int nf = 0; nf < 8; nf++)
#pragma unroll
            for (int i = 0; i < 4; i++) acc[mf][nf][i] = 0.f;

    const int crow = tid >> 2, coff = (tid & 3) * 8;   // 32 rows/pass

    uint4 ar[4], br[4];
#pragma unroll
    for (int p = 0; p < 4; p++) {
        ar[p] = *(const uint4*)(Ag + (size_t)(crow + p * 32) * K + coff);
        br[p] = *(const uint4*)(Bg + (size_t)(crow + p * 32) * K + coff);
    }

    const int arow_l = ((lane >> 3) & 1) * 8 + (lane & 7);
    const int akoff_l = (lane >> 4) * 8;
    const int brow_l = ((lane >> 4) & 1) * 8 + (lane & 7);
    const int bkoff_l = ((lane >> 3) & 1) * 8;

    const int nt = K / 32;
    for (int tile = 0; tile < nt; tile++) {
        const int buf = tile & 1;
        {
            __half* as = sh[buf][0];
            __half* bs = sh[buf][1];
#pragma unroll
            for (int p = 0; p < 4; p++) {
                *(uint4*)(as + (crow + p * 32) * 40 + coff) = ar[p];
                *(uint4*)(bs + (crow + p * 32) * 40 + coff) = br[p];
            }
        }
        if (tile + 1 < nt) {
            const __half* An = Ag + (tile + 1) * 32;
            const __half* Bn = Bg + (tile + 1) * 32;
#pragma unroll
            for (int p = 0; p < 4; p++) {
                ar[p] = *(const uint4*)(An + (size_t)(crow + p * 32) * K + coff);
                br[p] = *(const uint4*)(Bn + (size_t)(crow + p * 32) * K + coff);
            }
        }
        __syncthreads();

        const unsigned as0 = (unsigned)__cvta_generic_to_shared(sh[buf][0]);
        const unsigned bs0 = (unsigned)__cvta_generic_to_shared(sh[buf][1]);
#pragma unroll
        for (int kc = 0; kc < 2; kc++) {
            unsigned a[4][4];
#pragma unroll
            for (int mf = 0; mf < 4; mf++)
                ldsm4(a[mf], as0 + ((wm * 64 + mf * 16 + arow_l) * 40
                                    + kc * 16 + akoff_l) * 2);
#pragma unroll
            for (int nfp = 0; nfp < 4; nfp++) {
                unsigned bk[4];
                ldsm4(bk, bs0 + ((wn * 64 + nfp * 16 + brow_l) * 40
                                 + kc * 16 + bkoff_l) * 2);
#pragma unroll
                for (int mf = 0; mf < 4; mf++) {
                    mma16(acc[mf][2 * nfp],     a[mf], bk[0], bk[1]);
                    mma16(acc[mf][2 * nfp + 1], a[mf], bk[2], bk[3]);
                }
            }
        }
        __syncthreads();
    }

    if (mode == 0) {
#pragma unroll
        for (int mf = 0; mf < 4; mf++) {
            int row = blockIdx.y * 128 + wm * 64 + mf * 16 + g;
#pragma unroll
            for (int nf = 0; nf < 8; nf++) {
                int col = blockIdx.x * 128 + wn * 64 + nf * 8 + 2 * t;
                float b0 = bias[col], b1 = bias[col + 1];
                *(float2*)(Cf + (size_t)row * N + col) =
                    make_float2(acc[mf][nf][0] + b0, acc[mf][nf][1] + b1);
                *(float2*)(Cf + (size_t)(row + 8) * N + col) =
                    make_float2(acc[mf][nf][2] + b0, acc[mf][nf][3] + b1);
            }
        }
    } else {
        // fused QKV epilogue: bias + split + rope -> [b,h,l,d] fp16
#pragma unroll
        for (int nf = 0; nf < 8; nf++) {
            const int cg = blockIdx.x * 128 + wn * 64 + nf * 8 + 2 * t;
            const int sec = cg >> 10;          // 0=q, 1=k, 2=v
            const int d10 = cg & 1023;
            const int h = d10 >> 6, d = d10 & 63;
            const float b0 = bias[cg], b1 = bias[cg + 1];
            float inv = 0.f;
            if (sec < 2)
                inv = powf(10000.0f, -(float)d / (float)DH);  // d even = 2*i
#pragma unroll
            for (int mf = 0; mf < 4; mf++) {
#pragma unroll
                for (int rr = 0; rr < 2; rr++) {
                    int row = blockIdx.y * 128 + wm * 64 + mf * 16 + g + rr * 8;
                    int b = row >> 11, l = row & (NL - 1);
                    float v0 = acc[mf][nf][2 * rr] + b0;
                    float v1 = acc[mf][nf][2 * rr + 1] + b1;
                    size_t o = ((size_t)(b * NH + h) * NL + l) * DH + d;
                    if (sec == 2) {
                        *(unsigned*)(vh + o) = pack2(v0, v1);
                    } else {
                        float sn, cs;
                        sincosf((float)l * inv, &sn, &cs);
                        unsigned w = pack2(v0 * cs - v1 * sn,
                                           v0 * sn + v1 * cs);
                        *(unsigned*)((sec == 0 ? qh : kh) + o) = w;
                    }
                }
            }
        }
    }
}

// ---------------------------------------------------------------------------
// FP16 flash attention (unchanged from R11), fixed-max softmax.
// ---------------------------------------------------------------------------
#define QT 256
#define KT 64
#define STR 72   /* halfs per row */
#define SCL 0.1803368801111244f   /* 0.125 * log2(e) */

__global__ __launch_bounds__(256, 1) void attn_h(
    const __half* __restrict__ Qg, const __half* __restrict__ Kg,
    const __half* __restrict__ Vg, const int* __restrict__ amask,
    __half* __restrict__ outh)
{
    extern __shared__ __half sa[];
    const unsigned qs0 = (unsigned)__cvta_generic_to_shared(sa);
    const unsigned ks0 = qs0 + QT * STR * 2;
    const unsigned vs0 = ks0 + 2 * KT * STR * 2;
    float* msk = (float*)(sa + QT * STR + 4 * KT * STR);

    const int tid = threadIdx.x;
    const int lane = tid & 31, wid = tid >> 5;
    const int g = lane >> 2, t = lane & 3;
    const int qt = (gridDim.x - 1) - blockIdx.x;   // heavy tiles first
    const int bh = blockIdx.y;
    const int b = bh >> 4, h = bh & 15;
    const int q0 = qt * QT;
    const int ktmax = 4 * qt + 3;

    const __half* Qp = Qg + ((size_t)bh * NL + q0) * DH;
    const __half* Kp = Kg + (size_t)bh * NL * DH;
    const __half* Vp = Vg + (size_t)bh * NL * DH;

    auto copy_kv = [&](int kt_, int bf) {
        unsigned kd = ks0 + bf * (KT * STR * 2);
        unsigned vd = vs0 + bf * (KT * STR * 2);
        const __half* Ksrc = Kp + (size_t)kt_ * KT * DH;
        const __half* Vsrc = Vp + (size_t)kt_ * KT * DH;
#pragma unroll
        for (int i = 0; i < 2; i++) {
            int c = tid + i * 256;
            int r = c >> 3, o8 = (c & 7) * 8;
            cpa16(kd + (r * STR + o8) * 2, Ksrc + r * DH + o8);
            cpa16(vd + (r * STR + o8) * 2, Vsrc + r * DH + o8);
        }
        if (tid < KT)
            msk[bf * KT + tid] =
                amask[b * NL + kt_ * KT + tid] ? 0.f : -1e30f;
    };

    // prologue: Q + tile 0
#pragma unroll
    for (int i = 0; i < 8; i++) {
        int c = tid + i * 256;
        int r = c >> 3, o8 = (c & 7) * 8;
        cpa16(qs0 + (r * STR + o8) * 2, Qp + (size_t)r * DH + o8);
    }
    copy_kv(0, 0);
    CP_COMMIT();

    const int arow_l = ((lane >> 3) & 1) * 8 + (lane & 7);
    const int akoff_l = (lane >> 4) * 8;
    const int krow_l = ((lane >> 4) & 1) * 8 + (lane & 7);
    const int kkoff_l = ((lane >> 3) & 1) * 8;
    const int vkey_l = ((lane >> 4) & 1) * 8 + (lane & 7);
    const int vdoff_l = ((lane >> 3) & 1) * 8;

    unsigned qb[2];
#pragma unroll
    for (int mf = 0; mf < 2; mf++)
        qb[mf] = qs0 + ((wid * 32 + mf * 16 + arow_l) * STR + akoff_l) * 2;
    unsigned kbb[4], vbb[4];
#pragma unroll
    for (int j = 0; j < 4; j++) {
        kbb[j] = ks0 + ((j * 16 + krow_l) * STR + kkoff_l) * 2;
        vbb[j] = vs0 + (vkey_l * STR + j * 16 + vdoff_l) * 2;
    }
    const unsigned bufB = KT * STR * 2;

    float o[2][8][4];
#pragma unroll
    for (int mf = 0; mf < 2; mf++)
#pragma unroll
        for (int nf = 0; nf < 8; nf++)
#pragma unroll
            for (int i = 0; i < 4; i++) o[mf][nf][i] = 0.f;
    float l_acc[2][2] = {{0.f, 0.f}, {0.f, 0.f}};

    unsigned qreg[4][2][4];
    int buf = 0;
    for (int kt = 0; kt <= ktmax; kt++) {
        if (kt < ktmax) {
            copy_kv(kt + 1, buf ^ 1);
            CP_COMMIT();
            CP_WAIT1();
        } else {
            CP_WAIT0();
        }
        __syncthreads();

        if (kt == 0) {
#pragma unroll
            for (int kc = 0; kc < 4; kc++) {
                ldsm4(qreg[kc][0], qb[0] + kc * 32);
                ldsm4(qreg[kc][1], qb[1] + kc * 32);
            }
        }

        const unsigned kofs = buf * bufB;
        const float* mb = msk + buf * KT;

        float s[2][8][4];
#pragma unroll
        for (int mf = 0; mf < 2; mf++)
#pragma unroll
            for (int nf = 0; nf < 8; nf++)
#pragma unroll
                for (int i = 0; i < 4; i++) s[mf][nf][i] = 0.f;

#pragma unroll
        for (int kc = 0; kc < 4; kc++) {
            unsigned bk[4];
#pragma unroll
            for (int nfp = 0; nfp < 4; nfp++) {
                ldsm4(bk, kbb[nfp] + kofs + kc * 32);
                mma16(s[0][2 * nfp],     qreg[kc][0], bk[0], bk[1]);
                mma16(s[1][2 * nfp],     qreg[kc][1], bk[0], bk[1]);
                mma16(s[0][2 * nfp + 1], qreg[kc][0], bk[2], bk[3]);
                mma16(s[1][2 * nfp + 1], qreg[kc][1], bk[2], bk[3]);
            }
        }

        const bool diag = (kt * KT + KT - 1 > q0);

#pragma unroll
        for (int mf = 0; mf < 2; mf++) {
            const int rlo = q0 + wid * 32 + mf * 16 + g;
            const int rhi = rlo + 8;
            float sum0 = 0.f, sum1 = 0.f;
#pragma unroll
            for (int nf = 0; nf < 8; nf++) {
                int c = kt * KT + nf * 8 + 2 * t;
                float mk0 = mb[nf * 8 + 2 * t];
                float mk1 = mb[nf * 8 + 2 * t + 1];
                float* sv = s[mf][nf];
                sv[0] = sv[0] * SCL + mk0;
                sv[1] = sv[1] * SCL + mk1;
                sv[2] = sv[2] * SCL + mk0;
                sv[3] = sv[3] * SCL + mk1;
                if (diag) {
                    if (c     > rlo) sv[0] = -1e30f;
                    if (c + 1 > rlo) sv[1] = -1e30f;
                    if (c     > rhi) sv[2] = -1e30f;
                    if (c + 1 > rhi) sv[3] = -1e30f;
                }
                sv[0] = ex2(sv[0]); sum0 += sv[0];
                sv[1] = ex2(sv[1]); sum0 += sv[1];
                sv[2] = ex2(sv[2]); sum1 += sv[2];
                sv[3] = ex2(sv[3]); sum1 += sv[3];
            }
            l_acc[mf][0] += sum0;
            l_acc[mf][1] += sum1;
        }

#pragma unroll
        for (int kc = 0; kc < 4; kc++) {
            unsigned pa[2][4];
#pragma unroll
            for (int mf = 0; mf < 2; mf++) {
                pa[mf][0] = pack2(s[mf][2 * kc][0],     s[mf][2 * kc][1]);
                pa[mf][1] = pack2(s[mf][2 * kc][2],     s[mf][2 * kc][3]);
                pa[mf][2] = pack2(s[mf][2 * kc + 1][0], s[mf][2 * kc + 1][1]);
                pa[mf][3] = pack2(s[mf][2 * kc + 1][2], s[mf][2 * kc + 1][3]);
            }
#pragma unroll
            for (int db = 0; db < 4; db++) {
                unsigned bv[4];
                ldsm4t(bv, vbb[db] + kofs + kc * (16 * STR * 2));
                mma16(o[0][2 * db],     pa[0], bv[0], bv[2]);
                mma16(o[1][2 * db],     pa[1], bv[0], bv[2]);
                mma16(o[0][2 * db + 1], pa[0], bv[1], bv[3]);
                mma16(o[1][2 * db + 1], pa[1], bv[1], bv[3]);
            }
        }
        __syncthreads();
        buf ^= 1;
    }

#pragma unroll
    for (int mf = 0; mf < 2; mf++) {
        float s0 = l_acc[mf][0], s1 = l_acc[mf][1];
        s0 += __shfl_xor_sync(0xffffffffu, s0, 1);
        s0 += __shfl_xor_sync(0xffffffffu, s0, 2);
        s1 += __shfl_xor_sync(0xffffffffu, s1, 1);
        s1 += __shfl_xor_sync(0xffffffffu, s1, 2);
        float inv0 = 1.f / s0, inv1 = 1.f / s1;
        int rlo = q0 + wid * 32 + mf * 16 + g;
        __half* op = outh + ((size_t)b * NL + rlo) * ND + h * DH;
#pragma unroll
        for (int nf = 0; nf < 8; nf++) {
            int col = nf * 8 + 2 * t;
            *(unsigned*)(op + col) =
                pack2(o[mf][nf][0] * inv0, o[mf][nf][1] * inv0);
            *(unsigned*)(op + (size_t)8 * ND + col) =
                pack2(o[mf][nf][2] * inv1, o[mf][nf][3] * inv1);
        }
    }
}

// ---------------------------------------------------------------------------
extern "C" void kernel_launch(void* const* d_in, const int* in_sizes, int n_in,
                              void* d_out, int out_size)
{
    const float* x     = (const float*)d_in[0];
    const float* Wqkv  = (const float*)d_in[1];
    const float* bqkv  = (const float*)d_in[2];
    const float* Wproj = (const float*)d_in[3];
    const float* bproj = (const float*)d_in[4];
    const int*   amask = (const int*)d_in[5];
    float* out = (float*)d_out;

    __half *xh, *wqkvh, *wprojh, *qh, *kh, *vh, *attnh;
    cudaGetSymbolAddress((void**)&xh,     g_xh);
    cudaGetSymbolAddress((void**)&wqkvh,  g_wqkvh);
    cudaGetSymbolAddress((void**)&wprojh, g_wprojh);
    cudaGetSymbolAddress((void**)&qh,     g_qh);
    cudaGetSymbolAddress((void**)&kh,     g_kh);
    cudaGetSymbolAddress((void**)&vh,     g_vh);
    cudaGetSymbolAddress((void**)&attnh,  g_attnh);

    const int attn_smem = (QT * STR + 4 * KT * STR) * 2 + 2 * KT * 4;
    cudaFuncSetAttribute(attn_h,
                         cudaFuncAttributeMaxDynamicSharedMemorySize,
                         attn_smem);

    // Prep: convert x, transpose+convert weights
    int n8 = (NB * NL * ND) / 8;
    conv_h<<<(n8 + 255) / 256, 256>>>(x, xh, n8);
    wtrans_h<<<dim3(ND3 / 32, ND / 32), 256>>>(Wqkv, wqkvh, ND, ND3);
    wtrans_h<<<dim3(ND / 32, ND / 32), 256>>>(Wproj, wprojh, ND, ND);

    // 1) QKV projection with fused bias+split+RoPE -> qh/kh/vh [b,h,l,d]
    gemm_h<<<dim3(ND3 / 128, (NB * NL) / 128), 128>>>(
        xh, wqkvh, bqkv, nullptr, qh, kh, vh, NB * NL, ND3, ND, 1);

    // 2) Attention -> fp16 [b,l,nd]
    attn_h<<<dim3(NL / QT, NB * NH), 256, attn_smem>>>(
        qh, kh, vh, amask, attnh);

    // 3) Output projection -> fp32
    gemm_h<<<dim3(ND / 128, (NB * NL) / 128), 128>>>(
        attnh, wprojh, bproj, out, nullptr, nullptr, nullptr,
        NB * NL, ND, ND, 0);
}

// round 16
// speedup vs baseline: 1.3701x; 1.2152x over previous
#include <cuda_runtime.h>
#include <cuda_fp16.h>
#include <math.h>

#define NB 4
#define NL 2048
#define ND 1024
#define NH 16
#define DH 64
#define ND3 (3*ND)

// Scratch (allocation-free: __device__ globals)
__device__ uint4  g_xa    [(size_t)(NB*NL/16)*(ND/16)*32];  // x fragment-major
__device__ __half g_wqkvh [(size_t)ND3*ND];      // W_qkv^T fp16 [N][K]
__device__ __half g_wprojh[(size_t)ND*ND];       // W_proj^T fp16 [N][K]
__device__ __half g_qh    [(size_t)NB*NH*NL*DH]; // roped Q fp16 [b,h,l,d]
__device__ __half g_kh    [(size_t)NB*NH*NL*DH]; // roped K fp16 [b,h,l,d]
__device__ __half g_vh    [(size_t)NB*NH*NL*DH]; // V fp16 [b,h,l,d]
__device__ uint4  g_attnA [(size_t)(NB*NL/16)*(ND/16)*32];  // attn out frag-major

__device__ __forceinline__ unsigned pack2(float a, float b) {
    __half2 h = __floats2half2_rn(a, b);
    return *reinterpret_cast<unsigned*>(&h);
}
__device__ __forceinline__ float ex2(float x) {
    float y;
    asm("ex2.approx.f32 %0, %1;" : "=f"(y) : "f"(x));
    return y;
}
__device__ __forceinline__ void mma16(float* d, const unsigned* a,
                                      unsigned b0, unsigned b1) {
    asm volatile(
        "mma.sync.aligned.m16n8k16.row.col.f32.f16.f16.f32 "
        "{%0,%1,%2,%3}, {%4,%5,%6,%7}, {%8,%9}, {%0,%1,%2,%3};"
        : "+f"(d[0]), "+f"(d[1]), "+f"(d[2]), "+f"(d[3])
        : "r"(a[0]), "r"(a[1]), "r"(a[2]), "r"(a[3]), "r"(b0), "r"(b1));
}
__device__ __forceinline__ void ldsm4(unsigned* r, unsigned addr) {
    asm volatile(
        "ldmatrix.sync.aligned.m8n8.x4.shared.b16 {%0,%1,%2,%3}, [%4];"
        : "=r"(r[0]), "=r"(r[1]), "=r"(r[2]), "=r"(r[3]) : "r"(addr));
}
__device__ __forceinline__ void ldsm4t(unsigned* r, unsigned addr) {
    asm volatile(
        "ldmatrix.sync.aligned.m8n8.x4.trans.shared.b16 {%0,%1,%2,%3}, [%4];"
        : "=r"(r[0]), "=r"(r[1]), "=r"(r[2]), "=r"(r[3]) : "r"(addr));
}
__device__ __forceinline__ void cpa16(unsigned dst, const void* src) {
    asm volatile("cp.async.cg.shared.global [%0], [%1], 16;"
                 :: "r"(dst), "l"(src));
}
#define CP_COMMIT() asm volatile("cp.async.commit_group;")
#define CP_WAIT1()  asm volatile("cp.async.wait_group 1;")
#define CP_WAIT0()  asm volatile("cp.async.wait_group 0;")

// ---------------------------------------------------------------------------
// Prep: x fp32 [M][K] -> fragment-major fp16 uint4 [bm][bk][lane]
// lane l of block (bm,bk): a0=(r,c,c+1) a1=(r+8,..) a2=(r,c+8..) a3=(r+8,c+8..)
// with r=bm*16+l/4, c=bk*16+2*(l%4).
// ---------------------------------------------------------------------------
__global__ void conv_frag(const float* __restrict__ x,
                          uint4* __restrict__ dst, int M, int K)
{
    int idx = blockIdx.x * blockDim.x + threadIdx.x;
    int total = (M / 16) * (K / 16) * 32;
    if (idx >= total) return;
    int lane = idx & 31;
    int blk = idx >> 5;
    int KB = K / 16;
    int bk = blk % KB, bm = blk / KB;
    int r = bm * 16 + (lane >> 2);
    int c = bk * 16 + 2 * (lane & 3);
    const float* p = x + (size_t)r * K + c;
    float2 v00 = *(const float2*)(p);
    float2 v10 = *(const float2*)(p + (size_t)8 * K);
    float2 v01 = *(const float2*)(p + 8);
    float2 v11 = *(const float2*)(p + (size_t)8 * K + 8);
    uint4 w;
    w.x = pack2(v00.x, v00.y);
    w.y = pack2(v10.x, v10.y);
    w.z = pack2(v01.x, v01.y);
    w.w = pack2(v11.x, v11.y);
    dst[idx] = w;
}

// ---------------------------------------------------------------------------
// Prep: W [K][N] fp32 -> Wt [N][K] fp16
// ---------------------------------------------------------------------------
__global__ __launch_bounds__(256) void wtrans_h(
    const float* __restrict__ W, __half* __restrict__ Wt, int K, int N)
{
    __shared__ float sm[32][33];
    int tx = threadIdx.x & 31, ty = threadIdx.x >> 5;
    int n0 = blockIdx.x * 32, k0 = blockIdx.y * 32;
#pragma unroll
    for (int j = 0; j < 4; j++)
        sm[ty + 8 * j][tx] = W[(size_t)(k0 + ty + 8 * j) * N + n0 + tx];
    __syncthreads();
#pragma unroll
    for (int j = 0; j < 4; j++)
        Wt[(size_t)(n0 + ty + 8 * j) * K + k0 + tx] =
            __float2half(sm[tx][ty + 8 * j]);
}

// ---------------------------------------------------------------------------
// FP16 GEMM: C[M][N] = A[M][K] @ Bt[N][K]^T + bias[N].
// A comes pre-fragmented from gmem (no SMEM for A): one LDG.128 per (mf,kc)
// delivers the exact mma A-fragment. B staged via SMEM+LDSM (R11 geometry).
// CTA 128x128, BK=32, 8 warps (4m x 2n), warp tile 32x64, 2 CTAs/SM.
// mode 0: C fp32 [M][N].  mode 1: fused QKV bias+split+RoPE epilogue.
// ---------------------------------------------------------------------------
__global__ __launch_bounds__(256, 2) void gemm_h(
    const uint4* __restrict__ Af, const __half* __restrict__ Bt,
    const float* __restrict__ bias, float* __restrict__ Cf,
    __half* __restrict__ qh, __half* __restrict__ kh,
    __half* __restrict__ vh,
    int M, int N, int K, int mode)
{
    __shared__ __half sh[2][128 * 40];   // B only: [buf][row*40+k]  20.5KB
    const int tid = threadIdx.x;
    const int lane = tid & 31, wid = tid >> 5;
    const int wm = wid >> 1, wn = wid & 1;
    const int g = lane >> 2, t = lane & 3;
    const int KB = K / 16;

    const __half* Bg = Bt + (size_t)blockIdx.x * 128 * K;
    // A fragment base per mf: block row bm = blockIdx.y*8 + wm*2 + mf
    const uint4* Ab[2];
#pragma unroll
    for (int mf = 0; mf < 2; mf++)
        Ab[mf] = Af + ((size_t)(blockIdx.y * 8 + wm * 2 + mf) * KB) * 32 + lane;

    float acc[2][8][4];
#pragma unroll
    for (int mf = 0; mf < 2; mf++)
#pragma unroll
        for (int nf = 0; nf < 8; nf++)
#pragma unroll
            for (int i = 0; i < 4; i++) acc[mf][nf][i] = 0.f;

    const int crow = tid >> 2, coff = (tid & 3) * 8;

    uint4 br[2];
    br[0] = *(const uint4*)(Bg + (size_t)crow * K + coff);
    br[1] = *(const uint4*)(Bg + (size_t)(crow + 64) * K + coff);

    uint4 afc[2][2], afn[2][2];   // [kc][mf] current / next tile A fragments
#pragma unroll
    for (int kc = 0; kc < 2; kc++)
#pragma unroll
        for (int mf = 0; mf < 2; mf++)
            afc[kc][mf] = Ab[mf][(size_t)kc * 32];

    const int brow_l = ((lane >> 4) & 1) * 8 + (lane & 7);
    const int bkoff_l = ((lane >> 3) & 1) * 8;

    const int nt = K / 32;
    for (int tile = 0; tile < nt; tile++) {
        const int buf = tile & 1;
        {
            __half* bs = sh[buf];
            *(uint4*)(bs + crow * 40 + coff) = br[0];
            *(uint4*)(bs + (crow + 64) * 40 + coff) = br[1];
        }
        if (tile + 1 < nt) {
            const __half* Bn = Bg + (tile + 1) * 32;
            br[0] = *(const uint4*)(Bn + (size_t)crow * K + coff);
            br[1] = *(const uint4*)(Bn + (size_t)(crow + 64) * K + coff);
#pragma unroll
            for (int kc = 0; kc < 2; kc++)
#pragma unroll
                for (int mf = 0; mf < 2; mf++)
                    afn[kc][mf] = Ab[mf][(size_t)(2 * (tile + 1) + kc) * 32];
        }
        __syncthreads();

        const unsigned bs0 = (unsigned)__cvta_generic_to_shared(sh[buf]);
#pragma unroll
        for (int kc = 0; kc < 2; kc++) {
            unsigned a[2][4];
#pragma unroll
            for (int mf = 0; mf < 2; mf++) {
                a[mf][0] = afc[kc][mf].x;
                a[mf][1] = afc[kc][mf].y;
                a[mf][2] = afc[kc][mf].z;
                a[mf][3] = afc[kc][mf].w;
            }
#pragma unroll
            for (int nfp = 0; nfp < 4; nfp++) {
                unsigned bk[4];
                ldsm4(bk, bs0 + ((wn * 64 + nfp * 16 + brow_l) * 40
                                 + kc * 16 + bkoff_l) * 2);
#pragma unroll
                for (int mf = 0; mf < 2; mf++) {
                    mma16(acc[mf][2 * nfp],     a[mf], bk[0], bk[1]);
                    mma16(acc[mf][2 * nfp + 1], a[mf], bk[2], bk[3]);
                }
            }
        }
#pragma unroll
        for (int kc = 0; kc < 2; kc++)
#pragma unroll
            for (int mf = 0; mf < 2; mf++)
                afc[kc][mf] = afn[kc][mf];
    }

    if (mode == 0) {
#pragma unroll
        for (int mf = 0; mf < 2; mf++) {
            int row = blockIdx.y * 128 + wm * 32 + mf * 16 + g;
#pragma unroll
            for (int nf = 0; nf < 8; nf++) {
                int col = blockIdx.x * 128 + wn * 64 + nf * 8 + 2 * t;
                float b0 = bias[col], b1 = bias[col + 1];
                *(float2*)(Cf + (size_t)row * N + col) =
                    make_float2(acc[mf][nf][0] + b0, acc[mf][nf][1] + b1);
                *(float2*)(Cf + (size_t)(row + 8) * N + col) =
                    make_float2(acc[mf][nf][2] + b0, acc[mf][nf][3] + b1);
            }
        }
    } else {
        // fused QKV epilogue: bias + split + rope -> [b,h,l,d] fp16
#pragma unroll
        for (int nf = 0; nf < 8; nf++) {
            const int cg = blockIdx.x * 128 + wn * 64 + nf * 8 + 2 * t;
            const int sec = cg >> 10;          // 0=q, 1=k, 2=v
            const int d10 = cg & 1023;
            const int h = d10 >> 6, d = d10 & 63;
            const float b0 = bias[cg], b1 = bias[cg + 1];
            float inv = 0.f;
            if (sec < 2)
                inv = powf(10000.0f, -(float)d / (float)DH);  // d even = 2*i
#pragma unroll
            for (int mf = 0; mf < 2; mf++) {
#pragma unroll
                for (int rr = 0; rr < 2; rr++) {
                    int row = blockIdx.y * 128 + wm * 32 + mf * 16 + g + rr * 8;
                    int b = row >> 11, l = row & (NL - 1);
                    float v0 = acc[mf][nf][2 * rr] + b0;
                    float v1 = acc[mf][nf][2 * rr + 1] + b1;
                    size_t o = ((size_t)(b * NH + h) * NL + l) * DH + d;
                    if (sec == 2) {
                        *(unsigned*)(vh + o) = pack2(v0, v1);
                    } else {
                        float sn, cs;
                        sincosf((float)l * inv, &sn, &cs);
                        unsigned w = pack2(v0 * cs - v1 * sn,
                                           v0 * sn + v1 * cs);
                        *(unsigned*)((sec == 0 ? qh : kh) + o) = w;
                    }
                }
            }
        }
    }
}

// ---------------------------------------------------------------------------
// FP16 flash attention, fixed-max softmax, causal warp-skip. Output written
// fragment-major (= proj gemm's A operand layout; D frag == A frag, lane-id
// preserved). q-tile 256 (8 warps x 32 rows), key-tile 64, cp.async double
// buffer, Q hoisted to regs, K ldmatrix, V ldmatrix.trans, P from regs.
// ---------------------------------------------------------------------------
#define QT 256
#define KT 64
#define STR 72   /* halfs per row */
#define SCL 0.1803368801111244f   /* 0.125 * log2(e) */

__global__ __launch_bounds__(256, 1) void attn_h(
    const __half* __restrict__ Qg, const __half* __restrict__ Kg,
    const __half* __restrict__ Vg, const int* __restrict__ amask,
    uint4* __restrict__ outA)
{
    extern __shared__ __half sa[];
    const unsigned qs0 = (unsigned)__cvta_generic_to_shared(sa);
    const unsigned ks0 = qs0 + QT * STR * 2;
    const unsigned vs0 = ks0 + 2 * KT * STR * 2;
    float* msk = (float*)(sa + QT * STR + 4 * KT * STR);

    const int tid = threadIdx.x;
    const int lane = tid & 31, wid = tid >> 5;
    const int g = lane >> 2, t = lane & 3;
    const int qt = (gridDim.x - 1) - blockIdx.x;   // heavy tiles first
    const int bh = blockIdx.y;
    const int b = bh >> 4, h = bh & 15;
    const int q0 = qt * QT;
    const int ktmax = 4 * qt + 3;

    const __half* Qp = Qg + ((size_t)bh * NL + q0) * DH;
    const __half* Kp = Kg + (size_t)bh * NL * DH;
    const __half* Vp = Vg + (size_t)bh * NL * DH;

    auto copy_kv = [&](int kt_, int bf) {
        unsigned kd = ks0 + bf * (KT * STR * 2);
        unsigned vd = vs0 + bf * (KT * STR * 2);
        const __half* Ksrc = Kp + (size_t)kt_ * KT * DH;
        const __half* Vsrc = Vp + (size_t)kt_ * KT * DH;
#pragma unroll
        for (int i = 0; i < 2; i++) {
            int c = tid + i * 256;
            int r = c >> 3, o8 = (c & 7) * 8;
            cpa16(kd + (r * STR + o8) * 2, Ksrc + r * DH + o8);
            cpa16(vd + (r * STR + o8) * 2, Vsrc + r * DH + o8);
        }
        if (tid < KT)
            msk[bf * KT + tid] =
                amask[b * NL + kt_ * KT + tid] ? 0.f : -1e30f;
    };

    // prologue: Q + tile 0
#pragma unroll
    for (int i = 0; i < 8; i++) {
        int c = tid + i * 256;
        int r = c >> 3, o8 = (c & 7) * 8;
        cpa16(qs0 + (r * STR + o8) * 2, Qp + (size_t)r * DH + o8);
    }
    copy_kv(0, 0);
    CP_COMMIT();

    const int arow_l = ((lane >> 3) & 1) * 8 + (lane & 7);
    const int akoff_l = (lane >> 4) * 8;
    const int krow_l = ((lane >> 4) & 1) * 8 + (lane & 7);
    const int kkoff_l = ((lane >> 3) & 1) * 8;
    const int vkey_l = ((lane >> 4) & 1) * 8 + (lane & 7);
    const int vdoff_l = ((lane >> 3) & 1) * 8;

    unsigned qb[2];
#pragma unroll
    for (int mf = 0; mf < 2; mf++)
        qb[mf] = qs0 + ((wid * 32 + mf * 16 + arow_l) * STR + akoff_l) * 2;
    unsigned kbb[4], vbb[4];
#pragma unroll
    for (int j = 0; j < 4; j++) {
        kbb[j] = ks0 + ((j * 16 + krow_l) * STR + kkoff_l) * 2;
        vbb[j] = vs0 + (vkey_l * STR + j * 16 + vdoff_l) * 2;
    }
    const unsigned bufB = KT * STR * 2;

    float o[2][8][4];
#pragma unroll
    for (int mf = 0; mf < 2; mf++)
#pragma unroll
        for (int nf = 0; nf < 8; nf++)
#pragma unroll
            for (int i = 0; i < 4; i++) o[mf][nf][i] = 0.f;
    float l_acc[2][2] = {{0.f, 0.f}, {0.f, 0.f}};

    unsigned qreg[4][2][4];
    int buf = 0;
    for (int kt = 0; kt <= ktmax; kt++) {
        if (kt < ktmax) {
            copy_kv(kt + 1, buf ^ 1);
            CP_COMMIT();
            CP_WAIT1();
        } else {
            CP_WAIT0();
        }
        __syncthreads();

        if (kt == 0) {
#pragma unroll
            for (int kc = 0; kc < 4; kc++) {
                ldsm4(qreg[kc][0], qb[0] + kc * 32);
                ldsm4(qreg[kc][1], qb[1] + kc * 32);
            }
        }

        // causal warp-skip: this warp's 32 rows all < first key of the tile
        const bool active = (q0 + wid * 32 + 31) >= kt * KT;
        if (active) {
            const unsigned kofs = buf * bufB;
            const float* mb = msk + buf * KT;

            float s[2][8][4];
#pragma unroll
            for (int mf = 0; mf < 2; mf++)
#pragma unroll
                for (int nf = 0; nf < 8; nf++)
#pragma unroll
                    for (int i = 0; i < 4; i++) s[mf][nf][i] = 0.f;

#pragma unroll
            for (int kc = 0; kc < 4; kc++) {
                unsigned bk[4];
#pragma unroll
                for (int nfp = 0; nfp < 4; nfp++) {
                    ldsm4(bk, kbb[nfp] + kofs + kc * 32);
                    mma16(s[0][2 * nfp],     qreg[kc][0], bk[0], bk[1]);
                    mma16(s[1][2 * nfp],     qreg[kc][1], bk[0], bk[1]);
                    mma16(s[0][2 * nfp + 1], qreg[kc][0], bk[2], bk[3]);
                    mma16(s[1][2 * nfp + 1], qreg[kc][1], bk[2], bk[3]);
                }
            }

            const bool diag = (kt * KT + KT - 1 > q0);

#pragma unroll
            for (int mf = 0; mf < 2; mf++) {
                const int rlo = q0 + wid * 32 + mf * 16 + g;
                const int rhi = rlo + 8;
                float sum0 = 0.f, sum1 = 0.f;
#pragma unroll
                for (int nf = 0; nf < 8; nf++) {
                    int c = kt * KT + nf * 8 + 2 * t;
                    float mk0 = mb[nf * 8 + 2 * t];
                    float mk1 = mb[nf * 8 + 2 * t + 1];
                    float* sv = s[mf][nf];
                    sv[0] = sv[0] * SCL + mk0;
                    sv[1] = sv[1] * SCL + mk1;
                    sv[2] = sv[2] * SCL + mk0;
                    sv[3] = sv[3] * SCL + mk1;
                    if (diag) {
                        if (c     > rlo) sv[0] = -1e30f;
                        if (c + 1 > rlo) sv[1] = -1e30f;
                        if (c     > rhi) sv[2] = -1e30f;
                        if (c + 1 > rhi) sv[3] = -1e30f;
                    }
                    sv[0] = ex2(sv[0]); sum0 += sv[0];
                    sv[1] = ex2(sv[1]); sum0 += sv[1];
                    sv[2] = ex2(sv[2]); sum1 += sv[2];
                    sv[3] = ex2(sv[3]); sum1 += sv[3];
                }
                l_acc[mf][0] += sum0;
                l_acc[mf][1] += sum1;
            }

#pragma unroll
            for (int kc = 0; kc < 4; kc++) {
                unsigned pa[2][4];
#pragma unroll
                for (int mf = 0; mf < 2; mf++) {
                    pa[mf][0] = pack2(s[mf][2 * kc][0],     s[mf][2 * kc][1]);
                    pa[mf][1] = pack2(s[mf][2 * kc][2],     s[mf][2 * kc][3]);
                    pa[mf][2] = pack2(s[mf][2 * kc + 1][0], s[mf][2 * kc + 1][1]);
                    pa[mf][3] = pack2(s[mf][2 * kc + 1][2], s[mf][2 * kc + 1][3]);
                }
#pragma unroll
                for (int db = 0; db < 4; db++) {
                    unsigned bv[4];
                    ldsm4t(bv, vbb[db] + buf * bufB + kc * (16 * STR * 2));
                    mma16(o[0][2 * db],     pa[0], bv[0], bv[2]);
                    mma16(o[1][2 * db],     pa[1], bv[0], bv[2]);
                    mma16(o[0][2 * db + 1], pa[0], bv[1], bv[3]);
                    mma16(o[1][2 * db + 1], pa[1], bv[1], bv[3]);
                }
            }
        }
        __syncthreads();
        buf ^= 1;
    }

    // ---- finalize: fragment-major write (proj A operand layout) ----
#pragma unroll
    for (int mf = 0; mf < 2; mf++) {
        float s0 = l_acc[mf][0], s1 = l_acc[mf][1];
        s0 += __shfl_xor_sync(0xffffffffu, s0, 1);
        s0 += __shfl_xor_sync(0xffffffffu, s0, 2);
        s1 += __shfl_xor_sync(0xffffffffu, s1, 1);
        s1 += __shfl_xor_sync(0xffffffffu, s1, 2);
        float inv0 = 1.f / s0, inv1 = 1.f / s1;
        int bm = (b * NL + q0 + wid * 32 + mf * 16) >> 4;
        uint4* dst = outA + ((size_t)bm * (ND / 16) + h * 4) * 32 + lane;
#pragma unroll
        for (int j = 0; j < 4; j++) {
            uint4 w;
            w.x = pack2(o[mf][2 * j][0] * inv0,     o[mf][2 * j][1] * inv0);
            w.y = pack2(o[mf][2 * j][2] * inv1,     o[mf][2 * j][3] * inv1);
            w.z = pack2(o[mf][2 * j + 1][0] * inv0, o[mf][2 * j + 1][1] * inv0);
            w.w = pack2(o[mf][2 * j + 1][2] * inv1, o[mf][2 * j + 1][3] * inv1);
            dst[j * 32] = w;
        }
    }
}

// ---------------------------------------------------------------------------
extern "C" void kernel_launch(void* const* d_in, const int* in_sizes, int n_in,
                              void* d_out, int out_size)
{
    const float* x     = (const float*)d_in[0];
    const float* Wqkv  = (const float*)d_in[1];
    const float* bqkv  = (const float*)d_in[2];
    const float* Wproj = (const float*)d_in[3];
    const float* bproj = (const float*)d_in[4];
    const int*   amask = (const int*)d_in[5];
    float* out = (float*)d_out;

    uint4 *xa, *attnA;
    __half *wqkvh, *wprojh, *qh, *kh, *vh;
    cudaGetSymbolAddress((void**)&xa,     g_xa);
    cudaGetSymbolAddress((void**)&wqkvh,  g_wqkvh);
    cudaGetSymbolAddress((void**)&wprojh, g_wprojh);
    cudaGetSymbolAddress((void**)&qh,     g_qh);
    cudaGetSymbolAddress((void**)&kh,     g_kh);
    cudaGetSymbolAddress((void**)&vh,     g_vh);
    cudaGetSymbolAddress((void**)&attnA,  g_attnA);

    const int attn_smem = (QT * STR + 4 * KT * STR) * 2 + 2 * KT * 4;
    cudaFuncSetAttribute(attn_h,
                         cudaFuncAttributeMaxDynamicSharedMemorySize,
                         attn_smem);

    // Prep: x -> fragment-major fp16; weights -> [N][K] fp16
    int totf = (NB * NL / 16) * (ND / 16) * 32;
    conv_frag<<<(totf + 255) / 256, 256>>>(x, xa, NB * NL, ND);
    wtrans_h<<<dim3(ND3 / 32, ND / 32), 256>>>(Wqkv, wqkvh, ND, ND3);
    wtrans_h<<<dim3(ND / 32, ND / 32), 256>>>(Wproj, wprojh, ND, ND);

    // 1) QKV projection with fused bias+split+RoPE -> qh/kh/vh [b,h,l,d]
    gemm_h<<<dim3(ND3 / 128, (NB * NL) / 128), 256>>>(
        xa, wqkvh, bqkv, nullptr, qh, kh, vh, NB * NL, ND3, ND, 1);

    // 2) Attention -> fragment-major (proj A operand)
    attn_h<<<dim3(NL / QT, NB * NH), 256, attn_smem>>>(
        qh, kh, vh, amask, attnA);

    // 3) Output projection -> fp32
    gemm_h<<<dim3(ND / 128, (NB * NL) / 128), 256>>>(
        attnA, wprojh, bproj, out, nullptr, nullptr, nullptr,
        NB * NL, ND, ND, 0);
}